// round 17
// baseline (speedup 1.0000x reference)
#include <cuda_runtime.h>
#include <math.h>

#define BT 32
#define NP 2048
#define NC 7
#define KK 16
#define EPS 1e-5f

// Scratch (allocation-free rule: __device__ globals)
__device__ int   g_idx[BT * NP * KK];     // 4 MB
__device__ float g_u[BT * NP * 64];       // 16 MB  (BN1-folded x@(W1a-W1b)^T + t1)
__device__ float g_v[BT * NP * 64];       // 16 MB  (BN1-folded x@W1b^T)

__device__ __forceinline__ float gelu_exact(float x) {
    return 0.5f * x * (1.0f + erff(x * 0.7071067811865475f));
}

// ------------------------------------------------------------------
// Kernel 1: exact KNN, split-scan: 2 threads per query, each scans 1024
// candidates. Merge via bitonic half-cleaner: tau = max_i min(a_i, b_{15-i}).
// Pass B is set-based (downstream max-pool is order-invariant):
//   half0 strict-less  -> slots [0, cntA)            (forward)
//   half1 strict-less  -> slots [16-cntB, 16)        (backward)
//   ties at tau        -> gap slots [cntA, 16-cntB), smallest index first
// 128-thread blocks (64 queries) -> 1024 blocks for occupancy.
// ------------------------------------------------------------------
__global__ __launch_bounds__(128) void knn_kernel(const float* __restrict__ x) {
    __shared__ float4 pts[NP];          // 32 KB
    __shared__ int    tiebuf[128 * 8];  // 4 KB, exact-tie overflow

    const int b    = blockIdx.y;
    const int tid  = threadIdx.x;
    const int ql   = tid >> 1;          // query within block (0..63)
    const int half = tid & 1;           // which half of candidates
    const int p    = blockIdx.x * 64 + ql;

    for (int i = tid; i < NP; i += 128) {
        const float* row = x + ((size_t)b * NP + i) * NC;
        float X = row[0], Y = row[1], Z = row[2];
        pts[i] = make_float4(X, Y, Z, fmaf(Z, Z, fmaf(Y, Y, X * X)));
    }
    __syncthreads();

    const float4 me = pts[p];
    const float xp = me.x, yp = me.y, zp = me.z, sqp = me.w;
    const int q0 = half << 10;          // 0 or 1024

    float bd[KK];
    #pragma unroll
    for (int j = 0; j < KK; ++j) bd[j] = 3.402823466e+38f;
    float b15 = 3.402823466e+38f;

    // Pass A: 16 smallest distances over this thread's half (sorted asc)
    for (int q = q0; q < q0 + 1024; ++q) {
        float4 o = pts[q];
        float dot = fmaf(zp, o.z, fmaf(yp, o.y, xp * o.x));
        float d2  = fmaf(-2.0f, dot, sqp + o.w);
        if (d2 < b15) {
            float c = d2;
            #pragma unroll
            for (int j = 0; j < KK; ++j) {
                float t = bd[j];
                bd[j] = fminf(t, c);
                c     = fmaxf(t, c);
            }
            b15 = bd[KK - 1];
        }
    }

    // Merge across the thread pair: tau = 16th smallest of the union.
    // Half-cleaner: {min(a_i, b_{15-i})} is the multiset of the 16 smallest;
    // tau = max of it. Symmetric in (a,b), so both lanes get the same tau.
    float tau = -3.402823466e+38f;
    #pragma unroll
    for (int i = 0; i < KK; ++i) {
        float pb = __shfl_xor_sync(0xffffffffu, bd[KK - 1 - i], 1);
        tau = fmaxf(tau, fminf(bd[i], pb));
    }

    // Pass B: collect indices over this half. Strict-less total <= 15, so
    // forward (half0) and backward (half1) strict regions never collide.
    int cnt = 0, nt = 0;
    int* outp = g_idx + ((size_t)b * NP + p) * KK;
    for (int q = q0; q < q0 + 1024; ++q) {
        float4 o = pts[q];
        float dot = fmaf(zp, o.z, fmaf(yp, o.y, xp * o.x));
        float d2  = fmaf(-2.0f, dot, sqp + o.w);
        if (d2 < tau) {
            outp[half ? (KK - 1 - cnt) : cnt] = q;
            cnt++;
        } else if (d2 == tau) {
            if (nt < 8) tiebuf[tid * 8 + nt] = q;
            nt++;
        }
    }
    int cntO = __shfl_xor_sync(0xffffffffu, cnt, 1);
    int ntO  = __shfl_xor_sync(0xffffffffu, nt, 1);
    int cntA = half ? cntO : cnt;      // half0 strict count
    int cntB = half ? cnt  : cntO;     // half1 strict count
    int ntA  = half ? ntO  : nt;       // half0 tie count
    int rem  = KK - cntA - cntB;       // size of tie gap [cntA, 16-cntB)
    int myn  = min(nt, 8);
    int start, take;
    if (half == 0) {                   // half0 ties first (smaller indices)
        start = cntA;
        take  = min(myn, rem);
    } else {
        int aT = min(min(ntA, 8), rem);   // exactly what half0 wrote
        start = cntA + aT;
        take  = min(myn, rem - aT);
    }
    for (int t = 0; t < take; ++t)
        outp[start + t] = tiebuf[tid * 8 + t];
}

// ------------------------------------------------------------------
// Kernel 2: per-point u' = (x@(W1a-W1b)^T)*s1 + t1,  v' = (x@W1b^T)*s1
// ------------------------------------------------------------------
__global__ void uv_kernel(const float* __restrict__ x, const float* __restrict__ W1,
                          const float* __restrict__ g1, const float* __restrict__ b1,
                          const float* __restrict__ m1, const float* __restrict__ v1) {
    int id = blockIdx.x * blockDim.x + threadIdx.x;   // id = p*64 + o
    if (id >= BT * NP * 64) return;
    int o = id & 63;
    int p = id >> 6;

    float s1 = g1[o] * rsqrtf(v1[o] + EPS);
    float t1 = fmaf(-m1[o], s1, b1[o]);

    const float* xr = x + (size_t)p * NC;
    const float* w  = W1 + o * (2 * NC);
    float du = 0.f, dv = 0.f;
    #pragma unroll
    for (int c = 0; c < NC; ++c) {
        float xc = xr[c];
        float wb = w[NC + c];
        dv = fmaf(xc, wb, dv);
        du = fmaf(xc, w[c] - wb, du);
    }
    g_u[id] = fmaf(du, s1, t1);
    g_v[id] = dv * s1;
}

// ------------------------------------------------------------------
// Kernel 3: two independent 128-thread streams per 256-thread block, each
// stream pipelined over 16 points with its own named barrier (bar.sync 1/2)
// and disjoint smem — one stream's barrier/build stall is covered by the
// other stream's GEMM issue. Inner loop identical to R16 (f32x2 GEMM).
// h1 = gelu(u'[p] + v'[j]); h2 = h1 @ W2'^T (+t2);
// out = max(gelu(max_k h2), gelu(min_k h2))  [gelu valley-unimodal].
// ------------------------------------------------------------------
__global__ __launch_bounds__(256, 2) void mlp_kernel(
    const float* __restrict__ W2,
    const float* __restrict__ g2, const float* __restrict__ b2,
    const float* __restrict__ m2, const float* __restrict__ v2,
    float* __restrict__ out) {

    __shared__ __align__(16) float h1s[2][2][KK * 64];   // [stream][buf] 16 KB

    const int s   = threadIdx.x >> 7;      // stream 0/1
    const int wt  = threadIdx.x & 127;     // within-stream tid = output channel
    const int bid = 1 + s;                 // named barrier id

    float s2 = g2[wt] * rsqrtf(v2[wt] + EPS);
    float t2 = fmaf(-m2[wt], s2, b2[wt]);

    // Pack BN2-scaled W2 row into 32 x b64 registers (pairs of f32)
    unsigned long long w2r[32];
    const float* wrow = W2 + wt * 64;
    #pragma unroll
    for (int i = 0; i < 32; ++i) {
        float a  = wrow[2 * i]     * s2;
        float bb = wrow[2 * i + 1] * s2;
        asm("mov.b64 %0, {%1,%2};" : "=l"(w2r[i]) : "f"(a), "f"(bb));
    }

    const int g0    = blockIdx.x * 32 + s * 16;  // stream's 16 points (same batch)
    const int kq    = wt >> 3;                   // k index this thread builds
    const int c0    = (wt & 7) * 8;              // channel base this thread builds
    const int bbase = (g0 >> 11) << 11;          // batch * 2048
    const int lastg = BT * NP - 1;

    // Prologue: build h1 for point g0 into buffer 0
    {
        int nb = g_idx[(size_t)g0 * KK + kq];
        const float* vp = g_v + ((size_t)(bbase + nb) * 64 + c0);
        float4 va = *(const float4*)vp, vb = *(const float4*)(vp + 4);
        const float* up = g_u + ((size_t)g0 * 64 + c0);
        float4 ua = *(const float4*)up, ub = *(const float4*)(up + 4);
        float4 ra, rb;
        ra.x = gelu_exact(ua.x + va.x); ra.y = gelu_exact(ua.y + va.y);
        ra.z = gelu_exact(ua.z + va.z); ra.w = gelu_exact(ua.w + va.w);
        rb.x = gelu_exact(ub.x + vb.x); rb.y = gelu_exact(ub.y + vb.y);
        rb.z = gelu_exact(ub.z + vb.z); rb.w = gelu_exact(ub.w + vb.w);
        float* hp = &h1s[s][0][kq * 64 + c0];
        *(float4*)hp = ra; *(float4*)(hp + 4) = rb;
    }
    int nb1 = g_idx[(size_t)min(g0 + 1, lastg) * KK + kq];
    asm volatile("bar.sync %0, 128;" :: "r"(bid) : "memory");

    for (int pt = 0; pt < 16; ++pt) {
        const int buf = pt & 1;
        const int g   = g0 + pt;

        // Prefetch for point pt+1 (clamped indices: memory-safe, unused at pt=15)
        const int gp = min(g + 1, lastg);
        const float* vp = g_v + ((size_t)(bbase + nb1) * 64 + c0);
        float4 va = *(const float4*)vp, vb = *(const float4*)(vp + 4);
        const float* up = g_u + ((size_t)gp * 64 + c0);
        float4 ua = *(const float4*)up, ub = *(const float4*)(up + 4);
        int nb2 = g_idx[(size_t)min(g + 2, lastg) * KK + kq];

        // GEMM over h1s[s][buf] (broadcast LDS.128 + fma.rn.f32x2)
        const ulonglong2* h1u = reinterpret_cast<const ulonglong2*>(h1s[s][buf]);
        float vmx = -3.402823466e+38f, vmn = 3.402823466e+38f;
        #pragma unroll 4
        for (int k = 0; k < KK; ++k) {
            unsigned long long a0 = 0ULL, a1 = 0ULL, a2 = 0ULL, a3 = 0ULL;
            const ulonglong2* hk = h1u + k * 16;   // 64 floats = 16 x ull2
            #pragma unroll
            for (int i = 0; i < 16; ++i) {
                ulonglong2 hv = hk[i];
                if (i & 1) {
                    asm("fma.rn.f32x2 %0, %1, %2, %0;" : "+l"(a1) : "l"(hv.x), "l"(w2r[2 * i]));
                    asm("fma.rn.f32x2 %0, %1, %2, %0;" : "+l"(a3) : "l"(hv.y), "l"(w2r[2 * i + 1]));
                } else {
                    asm("fma.rn.f32x2 %0, %1, %2, %0;" : "+l"(a0) : "l"(hv.x), "l"(w2r[2 * i]));
                    asm("fma.rn.f32x2 %0, %1, %2, %0;" : "+l"(a2) : "l"(hv.y), "l"(w2r[2 * i + 1]));
                }
            }
            asm("add.rn.f32x2 %0, %0, %1;" : "+l"(a0) : "l"(a1));
            asm("add.rn.f32x2 %0, %0, %1;" : "+l"(a2) : "l"(a3));
            asm("add.rn.f32x2 %0, %0, %1;" : "+l"(a0) : "l"(a2));
            float f0, f1;
            asm("mov.b64 {%0,%1}, %2;" : "=f"(f0), "=f"(f1) : "l"(a0));
            float h2 = f0 + f1 + t2;
            vmx = fmaxf(vmx, h2);
            vmn = fminf(vmn, h2);
        }
        out[(size_t)g * 128 + wt] = fmaxf(gelu_exact(vmx), gelu_exact(vmn));

        // Build h1 for pt+1 into the other buffer (loads already in flight)
        {
            float4 ra, rb;
            ra.x = gelu_exact(ua.x + va.x); ra.y = gelu_exact(ua.y + va.y);
            ra.z = gelu_exact(ua.z + va.z); ra.w = gelu_exact(ua.w + va.w);
            rb.x = gelu_exact(ub.x + vb.x); rb.y = gelu_exact(ub.y + vb.y);
            rb.z = gelu_exact(ub.z + vb.z); rb.w = gelu_exact(ub.w + vb.w);
            float* hp = &h1s[s][buf ^ 1][kq * 64 + c0];
            *(float4*)hp = ra; *(float4*)(hp + 4) = rb;
        }
        nb1 = nb2;
        // stream-local barrier: writes to buf^1 visible before next GEMM
        asm volatile("bar.sync %0, 128;" :: "r"(bid) : "memory");
    }
}

// ------------------------------------------------------------------
extern "C" void kernel_launch(void* const* d_in, const int* in_sizes, int n_in,
                              void* d_out, int out_size) {
    const float* x   = (const float*)d_in[0];
    const float* W1  = (const float*)d_in[1];
    const float* g1  = (const float*)d_in[2];
    const float* b1  = (const float*)d_in[3];
    const float* m1  = (const float*)d_in[4];
    const float* v1  = (const float*)d_in[5];
    const float* W2  = (const float*)d_in[6];
    const float* g2  = (const float*)d_in[7];
    const float* b2  = (const float*)d_in[8];
    const float* m2  = (const float*)d_in[9];
    const float* v2  = (const float*)d_in[10];
    float* out = (float*)d_out;

    knn_kernel<<<dim3(NP / 64, BT), 128>>>(x);
    uv_kernel<<<(BT * NP * 64) / 256, 256>>>(x, W1, g1, b1, m1, v1);
    mlp_kernel<<<(BT * NP) / 32, 256>>>(W2, g2, b2, m2, v2, out);
}